// round 4
// baseline (speedup 1.0000x reference)
#include <cuda_runtime.h>
#include <math.h>

// Problem constants
#define BB      1024     // batch
#define T_TOT   576      // total timesteps (512 input + 64 task)
#define T_INP   512
#define T_TASK  64
#define HH      100      // hidden
#define HP      104      // hidden padded (16B-aligned rows for float4)
#define GG      400      // 4*H gates
#define WSTR    108      // W_h^T row stride (floats): 108%32=12 -> 4-phase LDS.128, 16B aligned
#define DF      9        // feature dim (in/task/out)
#define BS      7        // batch rows per block
#define NTHREADS 512
#define NBLOCKS  147     // ceil(1024/7); last block handles 2 rows

struct __align__(16) Smem {
    float whT[GG * WSTR];   // W_h transposed: whT[j*108 + k] = W_h[k*400 + j]   (172800 B)
    float h[BS * HP];       // hidden state, row-major, padded                   (2912 B)
    float z[BS * GG];       // per-step gate pre-activations                     (11200 B)
    float wout[HH * DF];    // W_out                                             (3600 B)
    float win[81];
    float wtask[81];
    float bin[DF];
    float btask[DF];
    float bout[DF];
    float s[BS * DF];       // encoded features for current timestep
    float raw[BS * DF];     // raw input/task features for next timestep (prefetched)
    float lg[BS * DF];      // logits
};
// total ~192 KB dynamic smem -> 1 block/SM

__device__ __forceinline__ float sigmoidf_(float x) {
    return __fdividef(1.0f, 1.0f + __expf(-x));
}
__device__ __forceinline__ float tanhf_(float x) {
    // 1 - 2/(1+e^{2x}) : exact at +-inf, ~1e-7 rel err, 2 MUFU
    return 1.0f - __fdividef(2.0f, 1.0f + __expf(2.0f * x));
}

__device__ __forceinline__ float gate_step(Smem* sm, int r, int u, float c) {
    const float* zr = &sm->z[r * GG + u];
    float gi = sigmoidf_(zr[0]);
    float gf = sigmoidf_(zr[HH]);
    float gg = tanhf_(zr[2 * HH]);
    float go = sigmoidf_(zr[3 * HH]);
    float cn = gf * c + gi * gg;
    sm->h[r * HP + u] = go * tanhf_(cn);
    return cn;
}

__global__ void __launch_bounds__(NTHREADS, 1)
lstm_fused_kernel(const float* __restrict__ input,  // [1024,512,9]
                  const float* __restrict__ task,   // [1024,64,9]
                  const float* __restrict__ W_in,   // [9,9]
                  const float* __restrict__ b_in,   // [9]
                  const float* __restrict__ W_task, // [9,9]
                  const float* __restrict__ b_task, // [9]
                  const float* __restrict__ W_x,    // [9,400]
                  const float* __restrict__ W_h,    // [100,400]
                  const float* __restrict__ b_lstm, // [400]
                  const float* __restrict__ W_out,  // [100,9]
                  const float* __restrict__ b_out,  // [9]
                  float* __restrict__ out)          // [1024,576,9]
{
    extern __shared__ unsigned char smem_raw[];
    Smem* sm = reinterpret_cast<Smem*>(smem_raw);

    const int tid  = threadIdx.x;
    const int bid  = blockIdx.x;
    const int row0 = bid * BS;
    const int nr   = min(BS, BB - row0);

    // ---------------- prologue: stage weights, zero state ----------------
    for (int idx = tid; idx < HH * GG; idx += NTHREADS) {
        int k = idx / GG;
        int j = idx - k * GG;
        sm->whT[j * WSTR + k] = W_h[idx];       // coalesced read, scattered STS (once)
    }
    for (int idx = tid; idx < HH * DF; idx += NTHREADS) sm->wout[idx] = W_out[idx];
    if (tid < 81) { sm->win[tid] = W_in[tid]; sm->wtask[tid] = W_task[tid]; }
    if (tid < DF) { sm->bin[tid] = b_in[tid]; sm->btask[tid] = b_task[tid]; sm->bout[tid] = b_out[tid]; }
    for (int idx = tid; idx < BS * HP; idx += NTHREADS) sm->h[idx] = 0.0f;
    if (tid < BS * DF) { sm->s[tid] = 0.0f; sm->raw[tid] = 0.0f; }

    // per-thread register constants
    float wx[9];
    float bl = 0.0f;
    if (tid < GG) {
#pragma unroll
        for (int f = 0; f < 9; f++) wx[f] = W_x[f * GG + tid];
        bl = b_lstm[tid];
    }
    // gate-unit ownership (c stays in registers across the whole scan)
    const int  gr0 = tid / HH, gu0 = tid - gr0 * HH;
    const int  u1  = tid + NTHREADS;
    const int  gr1 = u1 / HH, gu1 = u1 - gr1 * HH;
    const bool gv0 = (gr0 < nr);
    const bool gv1 = (u1 < BS * HH) && (gr1 < nr);
    float c0 = 0.0f, c1 = 0.0f;
    // phase-3 thread mappings
    const int lr = tid / 9, ld = tid - lr * 9;            // logits:   tid < 63
    const int sn = tid - 64;                              // s-next:   64 <= tid < 127
    const int sr = sn / 9, sf = sn - sr * 9;
    const int pf = tid - 448;                             // prefetch: 448 <= tid < 511
    const int pr = pf / 9, pff = pf - pr * 9;

    __syncthreads();

    // raw(t=0) then s(0)
    if (tid < nr * 9) sm->raw[tid] = input[(row0 + lr) * T_INP * 9 + ld];
    __syncthreads();
    if (tid < nr * 9) {
        float a = sm->bin[ld];
#pragma unroll
        for (int f2 = 0; f2 < 9; f2++) a += sm->raw[lr * 9 + f2] * sm->win[f2 * 9 + ld];
        sm->s[lr * 9 + ld] = fmaxf(a, 0.0f);
    }
    __syncthreads();

    // ---------------- the 576-step scan ----------------
    for (int t = 0; t < T_TOT; t++) {
        // ---- ph1: z[r][j] = b + s@W_x + h@W_h  (threads 0..399, one gate column each)
        if (tid < GG) {
            float acc[BS];
#pragma unroll
            for (int r = 0; r < BS; r++) acc[r] = bl;
#pragma unroll
            for (int f = 0; f < 9; f++) {
                float w = wx[f];
#pragma unroll
                for (int r = 0; r < BS; r++) acc[r] += sm->s[r * 9 + f] * w;
            }
            const float4* wr = reinterpret_cast<const float4*>(&sm->whT[tid * WSTR]);
#pragma unroll 5
            for (int kk = 0; kk < 25; kk++) {
                float4 w4 = wr[kk];
#pragma unroll
                for (int r = 0; r < BS; r++) {
                    float4 h4 = *reinterpret_cast<const float4*>(&sm->h[r * HP + kk * 4]);
                    acc[r] += w4.x * h4.x;
                    acc[r] += w4.y * h4.y;
                    acc[r] += w4.z * h4.z;
                    acc[r] += w4.w * h4.w;
                }
            }
#pragma unroll
            for (int r = 0; r < BS; r++) sm->z[r * GG + tid] = acc[r];
        }
        __syncthreads();

        // ---- ph2: gates (c in regs, h -> smem); last 2 warps also prefetch raw(t+1)
        if (gv0) c0 = gate_step(sm, gr0, gu0, c0);
        if (gv1) c1 = gate_step(sm, gr1, gu1, c1);
        if (pf >= 0 && pf < 63 && pr < nr && (t + 1) < T_TOT) {
            int tn = t + 1;
            float v = (tn < T_INP)
                          ? input[((row0 + pr) * T_INP + tn) * 9 + pff]
                          : task[((row0 + pr) * T_TASK + (tn - T_INP)) * 9 + pff];
            sm->raw[pf] = v;
        }
        __syncthreads();

        // ---- ph3a: logits (threads 0..62)  ||  encode s(t+1) (threads 64..126)
        if (tid < 63 && lr < nr) {
            const float* hr = &sm->h[lr * HP];
            float a0 = 0.f, a1 = 0.f, a2 = 0.f, a3 = 0.f;
#pragma unroll
            for (int k = 0; k < HH; k += 4) {
                a0 += hr[k]     * sm->wout[k * 9 + ld];
                a1 += hr[k + 1] * sm->wout[(k + 1) * 9 + ld];
                a2 += hr[k + 2] * sm->wout[(k + 2) * 9 + ld];
                a3 += hr[k + 3] * sm->wout[(k + 3) * 9 + ld];
            }
            sm->lg[lr * 9 + ld] = sm->bout[ld] + (a0 + a1) + (a2 + a3);
        } else if (sn >= 0 && sn < 63 && sr < nr && (t + 1) < T_TOT) {
            int tn = t + 1;
            const float* We = (tn < T_INP) ? sm->win : sm->wtask;
            const float* be = (tn < T_INP) ? sm->bin : sm->btask;
            float a = be[sf];
#pragma unroll
            for (int f2 = 0; f2 < 9; f2++) a += sm->raw[sr * 9 + f2] * We[f2 * 9 + sf];
            sm->s[sr * 9 + sf] = fmaxf(a, 0.0f);
        }
        __syncthreads();

        // ---- ph3b: softmax + store (one thread per row; no trailing barrier needed:
        //      next ph1 touches z/h/s only, all ordered by the barriers above)
        if (tid < nr) {
            float l[9];
            float m = -1e30f;
#pragma unroll
            for (int d = 0; d < 9; d++) { l[d] = sm->lg[tid * 9 + d]; m = fmaxf(m, l[d]); }
            float ssum = 0.0f;
#pragma unroll
            for (int d = 0; d < 9; d++) { l[d] = __expf(l[d] - m); ssum += l[d]; }
            float inv = __fdividef(1.0f, ssum);
            float* op = out + ((size_t)(row0 + tid) * T_TOT + t) * 9;
#pragma unroll
            for (int d = 0; d < 9; d++) op[d] = l[d] * inv;
        }
    }
}

extern "C" void kernel_launch(void* const* d_in, const int* in_sizes, int n_in,
                              void* d_out, int out_size) {
    const float* input  = (const float*)d_in[0];
    const float* task   = (const float*)d_in[1];
    const float* W_in   = (const float*)d_in[2];
    const float* b_in   = (const float*)d_in[3];
    const float* W_task = (const float*)d_in[4];
    const float* b_task = (const float*)d_in[5];
    const float* W_x    = (const float*)d_in[6];
    const float* W_h    = (const float*)d_in[7];
    const float* b_lstm = (const float*)d_in[8];
    const float* W_out  = (const float*)d_in[9];
    const float* b_out  = (const float*)d_in[10];
    float* out = (float*)d_out;

    cudaFuncSetAttribute(lstm_fused_kernel,
                         cudaFuncAttributeMaxDynamicSharedMemorySize,
                         (int)sizeof(Smem));
    lstm_fused_kernel<<<NBLOCKS, NTHREADS, sizeof(Smem)>>>(
        input, task, W_in, b_in, W_task, b_task,
        W_x, W_h, b_lstm, W_out, b_out, out);
}

// round 9
// speedup vs baseline: 1.0035x; 1.0035x over previous
#include <cuda_runtime.h>
#include <math.h>

// Problem constants
#define BB      1024     // batch
#define T_TOT   576      // total timesteps (512 input + 64 task)
#define T_INP   512
#define T_TASK  64
#define HH      100      // hidden
#define HP      104      // hidden padded (16B-aligned rows for float4)
#define GG      400      // 4*H gates
#define WSTR    108      // W_h^T row stride (floats): 108%32=12 -> 4-phase LDS.128, 16B aligned
#define DF      9        // feature dim (in/task/out)
#define BS      7        // batch rows per block
#define NTHREADS 512
#define NBLOCKS  147     // ceil(1024/7); last block handles 2 rows

struct __align__(16) Smem {
    float whT[GG * WSTR];   // W_h transposed: whT[j*108 + k] = W_h[k*400 + j]   (172800 B)
    float h[BS * HP];       // hidden state, row-major, padded                   (2912 B)
    float z[BS * GG];       // per-step gate pre-activations                     (11200 B)
    float wout[HH * DF];    // W_out                                             (3600 B)
    float win[81];
    float wtask[81];
    float bin[DF];
    float btask[DF];
    float bout[DF];
    float s[BS * DF];       // encoded features for current timestep
    float raw[BS * DF];     // raw input/task features for next timestep (prefetched)
    float lg[BS * DF];      // logits
};
// total ~192 KB dynamic smem -> 1 block/SM

__device__ __forceinline__ float sigmoidf_(float x) {
    return __fdividef(1.0f, 1.0f + __expf(-x));
}
__device__ __forceinline__ float tanhf_(float x) {
    // 1 - 2/(1+e^{2x}) : exact at +-inf, ~1e-7 rel err, 2 MUFU
    return 1.0f - __fdividef(2.0f, 1.0f + __expf(2.0f * x));
}

__device__ __forceinline__ float gate_step(Smem* sm, int r, int u, float c) {
    const float* zr = &sm->z[r * GG + u];
    float gi = sigmoidf_(zr[0]);
    float gf = sigmoidf_(zr[HH]);
    float gg = tanhf_(zr[2 * HH]);
    float go = sigmoidf_(zr[3 * HH]);
    float cn = gf * c + gi * gg;
    sm->h[r * HP + u] = go * tanhf_(cn);
    return cn;
}

__global__ void __launch_bounds__(NTHREADS, 1)
lstm_fused_kernel(const float* __restrict__ input,  // [1024,512,9]
                  const float* __restrict__ task,   // [1024,64,9]
                  const float* __restrict__ W_in,   // [9,9]
                  const float* __restrict__ b_in,   // [9]
                  const float* __restrict__ W_task, // [9,9]
                  const float* __restrict__ b_task, // [9]
                  const float* __restrict__ W_x,    // [9,400]
                  const float* __restrict__ W_h,    // [100,400]
                  const float* __restrict__ b_lstm, // [400]
                  const float* __restrict__ W_out,  // [100,9]
                  const float* __restrict__ b_out,  // [9]
                  float* __restrict__ out)          // [1024,576,9]
{
    extern __shared__ unsigned char smem_raw[];
    Smem* sm = reinterpret_cast<Smem*>(smem_raw);

    const int tid  = threadIdx.x;
    const int bid  = blockIdx.x;
    const int row0 = bid * BS;
    const int nr   = min(BS, BB - row0);

    // ---------------- prologue: stage weights, zero state ----------------
    for (int idx = tid; idx < HH * GG; idx += NTHREADS) {
        int k = idx / GG;
        int j = idx - k * GG;
        sm->whT[j * WSTR + k] = W_h[idx];       // coalesced read, scattered STS (once)
    }
    for (int idx = tid; idx < HH * DF; idx += NTHREADS) sm->wout[idx] = W_out[idx];
    if (tid < 81) { sm->win[tid] = W_in[tid]; sm->wtask[tid] = W_task[tid]; }
    if (tid < DF) { sm->bin[tid] = b_in[tid]; sm->btask[tid] = b_task[tid]; sm->bout[tid] = b_out[tid]; }
    for (int idx = tid; idx < BS * HP; idx += NTHREADS) sm->h[idx] = 0.0f;
    if (tid < BS * DF) { sm->s[tid] = 0.0f; sm->raw[tid] = 0.0f; }

    // per-thread register constants
    float wx[9];
    float bl = 0.0f;
    if (tid < GG) {
#pragma unroll
        for (int f = 0; f < 9; f++) wx[f] = W_x[f * GG + tid];
        bl = b_lstm[tid];
    }
    // gate-unit ownership (c stays in registers across the whole scan)
    const int  gr0 = tid / HH, gu0 = tid - gr0 * HH;
    const int  u1  = tid + NTHREADS;
    const int  gr1 = u1 / HH, gu1 = u1 - gr1 * HH;
    const bool gv0 = (gr0 < nr);
    const bool gv1 = (u1 < BS * HH) && (gr1 < nr);
    float c0 = 0.0f, c1 = 0.0f;
    // phase-3 thread mappings
    const int lr = tid / 9, ld = tid - lr * 9;            // logits:   tid < 63
    const int sn = tid - 64;                              // s-next:   64 <= tid < 127
    const int sr = sn / 9, sf = sn - sr * 9;
    const int pf = tid - 448;                             // prefetch: 448 <= tid < 511
    const int pr = pf / 9, pff = pf - pr * 9;

    __syncthreads();

    // raw(t=0) then s(0)
    if (tid < nr * 9) sm->raw[tid] = input[(row0 + lr) * T_INP * 9 + ld];
    __syncthreads();
    if (tid < nr * 9) {
        float a = sm->bin[ld];
#pragma unroll
        for (int f2 = 0; f2 < 9; f2++) a += sm->raw[lr * 9 + f2] * sm->win[f2 * 9 + ld];
        sm->s[lr * 9 + ld] = fmaxf(a, 0.0f);
    }
    __syncthreads();

    // ---------------- the 576-step scan ----------------
    for (int t = 0; t < T_TOT; t++) {
        // ---- ph1: z[r][j] = b + s@W_x + h@W_h  (threads 0..399, one gate column each)
        if (tid < GG) {
            float acc[BS];
#pragma unroll
            for (int r = 0; r < BS; r++) acc[r] = bl;
#pragma unroll
            for (int f = 0; f < 9; f++) {
                float w = wx[f];
#pragma unroll
                for (int r = 0; r < BS; r++) acc[r] += sm->s[r * 9 + f] * w;
            }
            const float4* wr = reinterpret_cast<const float4*>(&sm->whT[tid * WSTR]);
#pragma unroll 5
            for (int kk = 0; kk < 25; kk++) {
                float4 w4 = wr[kk];
#pragma unroll
                for (int r = 0; r < BS; r++) {
                    float4 h4 = *reinterpret_cast<const float4*>(&sm->h[r * HP + kk * 4]);
                    acc[r] += w4.x * h4.x;
                    acc[r] += w4.y * h4.y;
                    acc[r] += w4.z * h4.z;
                    acc[r] += w4.w * h4.w;
                }
            }
#pragma unroll
            for (int r = 0; r < BS; r++) sm->z[r * GG + tid] = acc[r];
        }
        __syncthreads();

        // ---- ph2: gates (c in regs, h -> smem); last 2 warps also prefetch raw(t+1)
        if (gv0) c0 = gate_step(sm, gr0, gu0, c0);
        if (gv1) c1 = gate_step(sm, gr1, gu1, c1);
        if (pf >= 0 && pf < 63 && pr < nr && (t + 1) < T_TOT) {
            int tn = t + 1;
            float v = (tn < T_INP)
                          ? input[((row0 + pr) * T_INP + tn) * 9 + pff]
                          : task[((row0 + pr) * T_TASK + (tn - T_INP)) * 9 + pff];
            sm->raw[pf] = v;
        }
        __syncthreads();

        // ---- ph3a: logits (threads 0..62)  ||  encode s(t+1) (threads 64..126)
        if (tid < 63 && lr < nr) {
            const float* hr = &sm->h[lr * HP];
            float a0 = 0.f, a1 = 0.f, a2 = 0.f, a3 = 0.f;
#pragma unroll
            for (int k = 0; k < HH; k += 4) {
                a0 += hr[k]     * sm->wout[k * 9 + ld];
                a1 += hr[k + 1] * sm->wout[(k + 1) * 9 + ld];
                a2 += hr[k + 2] * sm->wout[(k + 2) * 9 + ld];
                a3 += hr[k + 3] * sm->wout[(k + 3) * 9 + ld];
            }
            sm->lg[lr * 9 + ld] = sm->bout[ld] + (a0 + a1) + (a2 + a3);
        } else if (sn >= 0 && sn < 63 && sr < nr && (t + 1) < T_TOT) {
            int tn = t + 1;
            const float* We = (tn < T_INP) ? sm->win : sm->wtask;
            const float* be = (tn < T_INP) ? sm->bin : sm->btask;
            float a = be[sf];
#pragma unroll
            for (int f2 = 0; f2 < 9; f2++) a += sm->raw[sr * 9 + f2] * We[f2 * 9 + sf];
            sm->s[sr * 9 + sf] = fmaxf(a, 0.0f);
        }
        __syncthreads();

        // ---- ph3b: softmax + store (one thread per row; no trailing barrier needed:
        //      next ph1 touches z/h/s only, all ordered by the barriers above)
        if (tid < nr) {
            float l[9];
            float m = -1e30f;
#pragma unroll
            for (int d = 0; d < 9; d++) { l[d] = sm->lg[tid * 9 + d]; m = fmaxf(m, l[d]); }
            float ssum = 0.0f;
#pragma unroll
            for (int d = 0; d < 9; d++) { l[d] = __expf(l[d] - m); ssum += l[d]; }
            float inv = __fdividef(1.0f, ssum);
            float* op = out + ((size_t)(row0 + tid) * T_TOT + t) * 9;
#pragma unroll
            for (int d = 0; d < 9; d++) op[d] = l[d] * inv;
        }
    }
}

extern "C" void kernel_launch(void* const* d_in, const int* in_sizes, int n_in,
                              void* d_out, int out_size) {
    const float* input  = (const float*)d_in[0];
    const float* task   = (const float*)d_in[1];
    const float* W_in   = (const float*)d_in[2];
    const float* b_in   = (const float*)d_in[3];
    const float* W_task = (const float*)d_in[4];
    const float* b_task = (const float*)d_in[5];
    const float* W_x    = (const float*)d_in[6];
    const float* W_h    = (const float*)d_in[7];
    const float* b_lstm = (const float*)d_in[8];
    const float* W_out  = (const float*)d_in[9];
    const float* b_out  = (const float*)d_in[10];
    float* out = (float*)d_out;

    cudaFuncSetAttribute(lstm_fused_kernel,
                         cudaFuncAttributeMaxDynamicSharedMemorySize,
                         (int)sizeof(Smem));
    lstm_fused_kernel<<<NBLOCKS, NTHREADS, sizeof(Smem)>>>(
        input, task, W_in, b_in, W_task, b_task,
        W_x, W_h, b_lstm, W_out, b_out, out);
}